// round 5
// baseline (speedup 1.0000x reference)
#include <cuda_runtime.h>
#include <cuda_fp16.h>
#include <cstdint>
#include <cstddef>

// ---------------------------------------------------------------------------
// Problem dims
// ---------------------------------------------------------------------------
constexpr int L    = 2048;
constexpr int HID  = 3072;
constexpr int H    = 24;
constexpr int D    = 128;
constexpr int LIP  = 64;
constexpr int CTX  = 4096;
constexpr int W1N  = 3 * HID + 4 * HID;   // 21504
constexpr int MLPD = 4 * HID;             // 12288
constexpr int FW   = HID + MLPD;          // 15360

// ---------------------------------------------------------------------------
// Float scratch
// ---------------------------------------------------------------------------
constexpr size_t O_MOD   = 0;                                   // 9216
constexpr size_t O_H     = O_MOD   + (size_t)3 * HID;           // L*W1N
constexpr size_t O_S     = O_H     + (size_t)L * W1N;           // H*L*L
constexpr size_t O_ATTN1 = O_S     + (size_t)H * L * L;         // H*L*D
constexpr size_t O_IPKR  = O_ATTN1 + (size_t)H * L * D;         // LIP*HID
constexpr size_t O_IPVR  = O_IPKR  + (size_t)LIP * HID;
constexpr size_t O_S2    = O_IPVR  + (size_t)LIP * HID;         // H*L*LIP
constexpr size_t O_IPA   = O_S2    + (size_t)H * L * LIP;       // H*L*D
constexpr size_t O_Y     = O_IPA   + (size_t)H * L * D;         // L*HID
constexpr size_t SCRATCH_F = O_Y + (size_t)L * HID;

__device__ __align__(16) float g_scratch[SCRATCH_F];

// ---------------------------------------------------------------------------
// Half scratch
// ---------------------------------------------------------------------------
constexpr size_t HQ = (size_t)H * L * D;
constexpr size_t OH_XMOD  = 0;                                   // L*HID
constexpr size_t OH_W1    = OH_XMOD  + (size_t)L * HID;          // W1N*HID
constexpr size_t OH_W2    = OH_W1    + (size_t)W1N * HID;        // HID*FW
constexpr size_t OH_IPKW  = OH_W2    + (size_t)HID * FW;         // HID*CTX
constexpr size_t OH_IPVW  = OH_IPKW  + (size_t)HID * CTX;
constexpr size_t OH_IP    = OH_IPVW  + (size_t)HID * CTX;        // LIP*CTX
constexpr size_t OH_QR    = OH_IP    + (size_t)LIP * CTX;        // HQ
constexpr size_t OH_KR    = OH_QR    + HQ;
constexpr size_t OH_QNR   = OH_KR    + HQ;
constexpr size_t OH_VT    = OH_QNR   + HQ;
constexpr size_t OH_P     = OH_VT    + HQ;                       // H*L*L
constexpr size_t OH_IPK   = OH_P     + (size_t)H * L * L;        // H*LIP*D
constexpr size_t OH_IPVT  = OH_IPK   + (size_t)H * LIP * D;
constexpr size_t OH_P2    = OH_IPVT  + (size_t)H * LIP * D;      // H*L*LIP
constexpr size_t OH_FUSED = OH_P2    + (size_t)H * L * LIP;      // L*FW
constexpr size_t SCRATCH_H = OH_FUSED + (size_t)L * FW;

__device__ __align__(16) __half g_hscratch[SCRATCH_H];

// ---------------------------------------------------------------------------
// Helpers
// ---------------------------------------------------------------------------
__device__ __forceinline__ void mma16(float* c, const uint32_t* a,
                                      uint32_t b0, uint32_t b1) {
    asm volatile(
        "mma.sync.aligned.m16n8k16.row.col.f32.f16.f16.f32 "
        "{%0,%1,%2,%3}, {%4,%5,%6,%7}, {%8,%9}, {%0,%1,%2,%3};\n"
        : "+f"(c[0]), "+f"(c[1]), "+f"(c[2]), "+f"(c[3])
        : "r"(a[0]), "r"(a[1]), "r"(a[2]), "r"(a[3]),
          "r"(b0), "r"(b1));
}

__device__ __forceinline__ void ldsm_x4(uint32_t* r, uint32_t addr) {
    asm volatile("ldmatrix.sync.aligned.m8n8.x4.shared.b16 {%0,%1,%2,%3}, [%4];"
                 : "=r"(r[0]), "=r"(r[1]), "=r"(r[2]), "=r"(r[3])
                 : "r"(addr));
}

__device__ __forceinline__ void cp_async16(uint32_t dst, const void* src, bool pred) {
    int bytes = pred ? 16 : 0;
    asm volatile("cp.async.cg.shared.global [%0], [%1], 16, %2;\n"
                 :: "r"(dst), "l"(src), "r"(bytes));
}

__device__ __forceinline__ float blockReduceSum(float v, float* sh) {
    #pragma unroll
    for (int o = 16; o; o >>= 1) v += __shfl_xor_sync(0xffffffffu, v, o);
    int lane = threadIdx.x & 31, w = threadIdx.x >> 5;
    __syncthreads();
    if (lane == 0) sh[w] = v;
    __syncthreads();
    float r = 0.f;
    int nw = blockDim.x >> 5;
    for (int i = 0; i < nw; i++) r += sh[i];
    return r;
}

__device__ __forceinline__ float blockReduceMax(float v, float* sh) {
    #pragma unroll
    for (int o = 16; o; o >>= 1) v = fmaxf(v, __shfl_xor_sync(0xffffffffu, v, o));
    int lane = threadIdx.x & 31, w = threadIdx.x >> 5;
    __syncthreads();
    if (lane == 0) sh[w] = v;
    __syncthreads();
    float r = -INFINITY;
    int nw = blockDim.x >> 5;
    for (int i = 0; i < nw; i++) r = fmaxf(r, sh[i]);
    return r;
}

__device__ __forceinline__ float gelu_tanh(float x) {
    float t  = 0.7978845608028654f * (x + 0.044715f * x * x * x);
    float th = 1.f - 2.f / (__expf(2.f * t) + 1.f);
    return 0.5f * x * (1.0f + th);
}

// ---------------------------------------------------------------------------
// fp16 GEMM: C[M,N](f32) = A[M,K](f16,row) * B[N,K](f16,row)^T (+ bias)
// 128x128x64 tile, 256 threads (2x4 warps, warp tile 64x32),
// cp.async 3-stage ring, XOR-swizzled 128B rows (16B granules), ldmatrix.
// Dynamic smem: 3 * 32KB = 96KB -> 2 CTAs/SM.
// ---------------------------------------------------------------------------
constexpr int GSTAGES   = 3;
constexpr int TILE_B    = 128 * 128;           // 16KB per matrix tile
constexpr int STAGE_B   = 2 * TILE_B;          // 32KB per stage
constexpr uint32_t GEMM_SMEM = GSTAGES * STAGE_B;   // 96KB

__global__ void __launch_bounds__(256, 2) gemm_f16_kernel(
    const __half* __restrict__ A, const __half* __restrict__ B,
    float* __restrict__ C, const float* __restrict__ bias,
    int M, int N, int K, int lda, int ldb, int ldc,
    size_t sA, size_t sB, size_t sC,
    int nTiles, int mc)
{
    extern __shared__ __align__(128) uint8_t dsm[];
    uint32_t smBase = (uint32_t)__cvta_generic_to_shared(dsm);

    A += (size_t)blockIdx.z * sA;
    B += (size_t)blockIdx.z * sB;
    C += (size_t)blockIdx.z * sC;

    int bx    = blockIdx.x;
    int per   = mc * nTiles;
    int chunk = bx / per;
    int rem   = bx - chunk * per;
    int nTile = rem / mc;
    int mTile = chunk * mc + (rem - nTile * mc);
    int aBase = mTile * 128;
    int bBase = nTile * 128;

    int tid  = threadIdx.x;
    int lane = tid & 31, warp = tid >> 5;
    int wm   = warp >> 2, wn = warp & 3;

    int kt = K >> 6;                    // K-iterations of 64

    // cp.async mapping: thread t loads row t>>1, 4 chunks of 16B (64B)
    // per matrix per k-iter.
    int ldRow = tid >> 1;               // 0..127
    int c0    = (tid & 1) * 4;          // 0 or 4
    int ldrb  = ldRow & 7;
    bool pa = aBase + ldRow < M;
    bool pb = bBase + ldRow < N;
    const __half* Ap = A + (size_t)(pa ? aBase + ldRow : 0) * lda + c0 * 8;
    const __half* Bp = B + (size_t)(pb ? bBase + ldRow : 0) * ldb + c0 * 8;
    uint32_t dRow = (uint32_t)ldRow * 128u;

#define GEMM_PREF(itv) do {                                                    \
    int _it = (itv);                                                           \
    if (_it < kt) {                                                            \
        uint32_t _st = smBase + (uint32_t)(_it % GSTAGES) * STAGE_B;           \
        size_t _ko = (size_t)_it * 64;                                         \
        _Pragma("unroll")                                                      \
        for (int _j = 0; _j < 4; _j++) {                                       \
            uint32_t _sw = (uint32_t)(((c0 + _j) ^ ldrb) << 4);                \
            cp_async16(_st + dRow + _sw, Ap + _ko + _j * 8, pa);               \
            cp_async16(_st + TILE_B + dRow + _sw, Bp + _ko + _j * 8, pb);      \
        }                                                                      \
    }                                                                          \
    asm volatile("cp.async.commit_group;\n" ::);                               \
} while (0)

    // ldmatrix base offsets (within a stage)
    int h    = lane >> 4;                       // k-half select
    int arow = wm * 64 + (lane & 15);
    int brow = wn * 32 + (lane & 15);
    int arb  = arow & 7;
    int brb  = brow & 7;
    uint32_t aRowOff = (uint32_t)arow * 128u;
    uint32_t bRowOff = (uint32_t)brow * 128u + (uint32_t)TILE_B;

    float acc[4][4][4];
    #pragma unroll
    for (int i = 0; i < 4; i++)
        #pragma unroll
        for (int j = 0; j < 4; j++)
            #pragma unroll
            for (int t = 0; t < 4; t++) acc[i][j][t] = 0.f;

    GEMM_PREF(0);
    GEMM_PREF(1);

    for (int it = 0; it < kt; ++it) {
        asm volatile("cp.async.wait_group 1;\n" ::);
        __syncthreads();
        GEMM_PREF(it + 2);

        uint32_t st = smBase + (uint32_t)(it % GSTAGES) * STAGE_B;

        #pragma unroll
        for (int kk = 0; kk < 4; kk++) {          // four k16 steps per BK=64
            uint32_t a[4][4], b[2][4];
            uint32_t ca = (uint32_t)(((kk * 2 + h) ^ arb) << 4);
            uint32_t cb = (uint32_t)(((kk * 2 + h) ^ brb) << 4);
            #pragma unroll
            for (int mt = 0; mt < 4; mt++)
                ldsm_x4(a[mt], st + aRowOff + mt * 2048u + ca);
            #pragma unroll
            for (int np = 0; np < 2; np++)
                ldsm_x4(b[np], st + bRowOff + np * 2048u + cb);
            #pragma unroll
            for (int mt = 0; mt < 4; mt++)
                #pragma unroll
                for (int nt = 0; nt < 4; nt++)
                    mma16(acc[mt][nt], a[mt],
                          b[nt >> 1][nt & 1], b[nt >> 1][(nt & 1) + 2]);
        }
    }
#undef GEMM_PREF

    // Epilogue
    int gid = lane >> 2, tig = lane & 3;
    #pragma unroll
    for (int mt = 0; mt < 4; mt++) {
        #pragma unroll
        for (int nt = 0; nt < 4; nt++) {
            int row = aBase + wm * 64 + mt * 16 + gid;
            int col = bBase + wn * 32 + nt * 8 + tig * 2;
            if (col < N) {
                float b0 = 0.f, b1 = 0.f;
                if (bias) { b0 = bias[col]; b1 = bias[col + 1]; }
                if (row < M) {
                    C[(size_t)row * ldc + col]     = acc[mt][nt][0] + b0;
                    C[(size_t)row * ldc + col + 1] = acc[mt][nt][1] + b1;
                }
                if (row + 8 < M) {
                    C[(size_t)(row + 8) * ldc + col]     = acc[mt][nt][2] + b0;
                    C[(size_t)(row + 8) * ldc + col + 1] = acc[mt][nt][3] + b1;
                }
            }
        }
    }
}

// ---------------------------------------------------------------------------
// float -> half conversion (n divisible by 4)
// ---------------------------------------------------------------------------
__global__ __launch_bounds__(256) void f2h_kernel(
    const float* __restrict__ in, __half* __restrict__ out, int n)
{
    int i = (blockIdx.x * 256 + threadIdx.x) * 4;
    if (i < n) {
        float4 v = *(const float4*)(in + i);
        *(__half2*)(out + i)     = __floats2half2_rn(v.x, v.y);
        *(__half2*)(out + i + 2) = __floats2half2_rn(v.z, v.w);
    }
}

// ---------------------------------------------------------------------------
// mod = silu(vec) @ mod_lin_w^T + mod_lin_b
// ---------------------------------------------------------------------------
__global__ __launch_bounds__(256) void mod_gemv_kernel(
    const float* __restrict__ vec, const float* __restrict__ W,
    const float* __restrict__ b, float* __restrict__ mod)
{
    __shared__ float sv[HID];
    int tid = threadIdx.x;
    for (int i = tid; i < HID; i += 256) {
        float x = vec[i];
        sv[i] = x / (1.f + __expf(-x));
    }
    __syncthreads();
    int warp = tid >> 5, lane = tid & 31;
    int n = blockIdx.x * 8 + warp;
    const float* wrow = W + (size_t)n * HID;
    float s = 0.f;
    for (int k = lane * 4; k < HID; k += 128) {
        float4 w4 = *(const float4*)(wrow + k);
        s += sv[k] * w4.x + sv[k + 1] * w4.y + sv[k + 2] * w4.z + sv[k + 3] * w4.w;
    }
    #pragma unroll
    for (int o = 16; o; o >>= 1) s += __shfl_xor_sync(0xffffffffu, s, o);
    if (lane == 0) mod[n] = s + b[n];
}

// ---------------------------------------------------------------------------
// x_mod = (1+scale)*layernorm(x) + shift  -> half
// ---------------------------------------------------------------------------
__global__ __launch_bounds__(256) void ln_mod_kernel(
    const float* __restrict__ x, const float* __restrict__ mod,
    __half* __restrict__ xmod)
{
    __shared__ float sh[8];
    int l = blockIdx.x, tid = threadIdx.x;
    const float* row = x + (size_t)l * HID;
    float v[12];
    float s = 0.f, sq = 0.f;
    #pragma unroll
    for (int i = 0; i < 12; i++) {
        v[i] = row[tid + i * 256];
        s += v[i];
        sq += v[i] * v[i];
    }
    s  = blockReduceSum(s, sh);
    sq = blockReduceSum(sq, sh);
    float mu   = s * (1.f / HID);
    float var  = sq * (1.f / HID) - mu * mu;
    float rstd = rsqrtf(var + 1e-6f);
    #pragma unroll
    for (int i = 0; i < 12; i++) {
        int c = tid + i * 256;
        float xn = (v[i] - mu) * rstd;
        xmod[(size_t)l * HID + c] = __float2half((1.f + mod[HID + c]) * xn + mod[c]);
    }
}

// ---------------------------------------------------------------------------
// rmsnorm(q,k) + rope + repack (half outputs). One warp per (l, head).
// q outputs pre-scaled by 1/sqrt(D).
// ---------------------------------------------------------------------------
__global__ __launch_bounds__(256) void rms_rope_kernel(
    const float* __restrict__ h, const float* __restrict__ pe,
    const float* __restrict__ qsc, const float* __restrict__ ksc,
    __half* __restrict__ qr, __half* __restrict__ kr,
    __half* __restrict__ qnr, __half* __restrict__ vt)
{
    int tid = threadIdx.x, lane = tid & 31, warp = tid >> 5;
    int g = blockIdx.x * 8 + warp;          // 0 .. H*L-1
    int l = g / H, head = g - l * H;

    const float* base = h + (size_t)l * W1N + head * D + lane * 4;
    float4 q = *(const float4*)(base);
    float4 k = *(const float4*)(base + HID);
    float4 v = *(const float4*)(base + 2 * HID);

    float sq = q.x * q.x + q.y * q.y + q.z * q.z + q.w * q.w;
    float sk = k.x * k.x + k.y * k.y + k.z * k.z + k.w * k.w;
    #pragma unroll
    for (int o = 16; o; o >>= 1) {
        sq += __shfl_xor_sync(0xffffffffu, sq, o);
        sk += __shfl_xor_sync(0xffffffffu, sk, o);
    }
    float rq = rsqrtf(sq * (1.f / D) + 1e-6f) * 0.08838834764831845f;
    float rk = rsqrtf(sk * (1.f / D) + 1e-6f);

    float4 qs4 = *(const float4*)(qsc + lane * 4);
    float4 ks4 = *(const float4*)(ksc + lane * 4);
    float4 qn = make_float4(q.x * rq * qs4.x, q.y * rq * qs4.y,
                            q.z * rq * qs4.z, q.w * rq * qs4.w);
    float4 kn = make_float4(k.x * rk * ks4.x, k.y * rk * ks4.y,
                            k.z * rk * ks4.z, k.w * rk * ks4.w);

    size_t oidx = ((size_t)head * L + l) * D + lane * 4;
    *(__half2*)(qnr + oidx)     = __floats2half2_rn(qn.x, qn.y);
    *(__half2*)(qnr + oidx + 2) = __floats2half2_rn(qn.z, qn.w);

    const float* pb = pe + ((size_t)l * (D / 2) + lane * 2) * 4;
    float4 p0 = *(const float4*)(pb);
    float4 p1 = *(const float4*)(pb + 4);

    float4 qo, ko;
    qo.x = p0.x * qn.x + p0.y * qn.y;  qo.y = p0.z * qn.x + p0.w * qn.y;
    qo.z = p1.x * qn.z + p1.y * qn.w;  qo.w = p1.z * qn.z + p1.w * qn.w;
    ko.x = p0.x * kn.x + p0.y * kn.y;  ko.y = p0.z * kn.x + p0.w * kn.y;
    ko.z = p1.x * kn.z + p1.y * kn.w;  ko.w = p1.z * kn.z + p1.w * kn.w;

    *(__half2*)(qr + oidx)     = __floats2half2_rn(qo.x, qo.y);
    *(__half2*)(qr + oidx + 2) = __floats2half2_rn(qo.z, qo.w);
    *(__half2*)(kr + oidx)     = __floats2half2_rn(ko.x, ko.y);
    *(__half2*)(kr + oidx + 2) = __floats2half2_rn(ko.z, ko.w);

    int d = lane * 4;
    size_t vb = ((size_t)head * D + d) * L + l;
    vt[vb]         = __float2half(v.x);
    vt[vb + L]     = __float2half(v.y);
    vt[vb + 2 * L] = __float2half(v.z);
    vt[vb + 3 * L] = __float2half(v.w);
}

// ---------------------------------------------------------------------------
// repack ip_k / ip_v GEMM outputs into per-head half layouts
// ---------------------------------------------------------------------------
__global__ __launch_bounds__(256) void repack_ip_kernel(
    const float* __restrict__ kraw, const float* __restrict__ vraw,
    __half* __restrict__ ipk, __half* __restrict__ ipvt)
{
    int i = blockIdx.x * 256 + threadIdx.x;       // < H*LIP*D
    int d = i & (D - 1);
    int lip = (i >> 7) & (LIP - 1);
    int head = i >> 13;
    size_t src = (size_t)lip * HID + head * D + d;
    ipk[((size_t)head * LIP + lip) * D + d]  = __float2half(kraw[src]);
    ipvt[((size_t)head * D + d) * LIP + lip] = __float2half(vraw[src]);
}

// ---------------------------------------------------------------------------
// row softmax float -> half
// ---------------------------------------------------------------------------
__global__ __launch_bounds__(256) void softmax_kernel(
    const float* __restrict__ S, __half* __restrict__ P, int ncols)
{
    __shared__ float sh[8];
    size_t row = blockIdx.x;
    const float* p = S + row * (size_t)ncols;
    __half* po = P + row * (size_t)ncols;
    float v[8];
    int cnt = 0;
    float m = -INFINITY;
    for (int c = threadIdx.x; c < ncols; c += 256) {
        v[cnt] = p[c];
        m = fmaxf(m, v[cnt]);
        cnt++;
    }
    m = blockReduceMax(m, sh);
    float s = 0.f;
    for (int i = 0; i < cnt; i++) {
        v[i] = __expf(v[i] - m);
        s += v[i];
    }
    s = blockReduceSum(s, sh);
    float inv = 1.f / s;
    cnt = 0;
    for (int c = threadIdx.x; c < ncols; c += 256) po[c] = __float2half(v[cnt++] * inv);
}

// ---------------------------------------------------------------------------
// fused = concat(attn1 + ip_scale*ip_attn, gelu(mlp)) -> half
// ---------------------------------------------------------------------------
__global__ __launch_bounds__(256) void fuse_kernel(
    const float* __restrict__ attn1, const float* __restrict__ ipattn,
    const float* __restrict__ ip_scale, const float* __restrict__ h,
    __half* __restrict__ fused)
{
    int c = blockIdx.x * 256 + threadIdx.x;   // 0..FW-1
    int l = blockIdx.y;
    float val;
    if (c < HID) {
        int head = c >> 7, d = c & (D - 1);
        size_t idx = ((size_t)head * L + l) * D + d;
        val = attn1[idx] + ip_scale[0] * ipattn[idx];
    } else {
        val = gelu_tanh(h[(size_t)l * W1N + 3 * HID + (c - HID)]);
    }
    fused[(size_t)l * FW + c] = __float2half(val);
}

// ---------------------------------------------------------------------------
// out = x + gate * y
// ---------------------------------------------------------------------------
__global__ __launch_bounds__(256) void final_kernel(
    const float* __restrict__ x, const float* __restrict__ mod,
    const float* __restrict__ y, float* __restrict__ out)
{
    int c = blockIdx.x * 256 + threadIdx.x;
    int l = blockIdx.y;
    size_t idx = (size_t)l * HID + c;
    out[idx] = x[idx] + mod[2 * HID + c] * y[idx];
}

// ---------------------------------------------------------------------------
// host side
// ---------------------------------------------------------------------------
static void launch_gemm(const __half* A, const __half* B, float* C, const float* bias,
                        int M, int N, int K, int lda, int ldb, int ldc,
                        size_t sA, size_t sB, size_t sC, int batch, int mc)
{
    int mTiles = (M + 127) / 128, nTiles = (N + 127) / 128;
    if (mc > mTiles) mc = mTiles;
    dim3 grid(mTiles * nTiles, 1, batch);
    gemm_f16_kernel<<<grid, 256, GEMM_SMEM>>>(A, B, C, bias, M, N, K, lda, ldb, ldc,
                                              sA, sB, sC, nTiles, mc);
}

static void launch_f2h(const float* in, __half* out, size_t n)
{
    int blocks = (int)((n / 4 + 255) / 256);
    f2h_kernel<<<blocks, 256>>>(in, out, (int)n);
}

extern "C" void kernel_launch(void* const* d_in, const int* in_sizes, int n_in,
                              void* d_out, int out_size)
{
    const float* x          = (const float*)d_in[0];
    const float* vec        = (const float*)d_in[1];
    const float* pe         = (const float*)d_in[2];
    const float* image_proj = (const float*)d_in[3];
    const float* ip_scale   = (const float*)d_in[4];
    const float* mod_w      = (const float*)d_in[5];
    const float* mod_b      = (const float*)d_in[6];
    const float* w1         = (const float*)d_in[7];
    const float* b1         = (const float*)d_in[8];
    const float* w2         = (const float*)d_in[9];
    const float* b2         = (const float*)d_in[10];
    const float* qsc        = (const float*)d_in[11];
    const float* ksc        = (const float*)d_in[12];
    const float* ipkw       = (const float*)d_in[13];
    const float* ipvw       = (const float*)d_in[14];
    float* out = (float*)d_out;

    cudaFuncSetAttribute(gemm_f16_kernel,
                         cudaFuncAttributeMaxDynamicSharedMemorySize, GEMM_SMEM);

    float* sc = nullptr;
    cudaGetSymbolAddress((void**)&sc, g_scratch);
    __half* hs = nullptr;
    cudaGetSymbolAddress((void**)&hs, g_hscratch);

    float* mod    = sc + O_MOD;
    float* hbuf   = sc + O_H;
    float* Sbuf   = sc + O_S;
    float* attn1  = sc + O_ATTN1;
    float* ipkr   = sc + O_IPKR;
    float* ipvr   = sc + O_IPVR;
    float* S2     = sc + O_S2;
    float* ipattn = sc + O_IPA;
    float* ybuf   = sc + O_Y;

    __half* h_xmod  = hs + OH_XMOD;
    __half* h_w1    = hs + OH_W1;
    __half* h_w2    = hs + OH_W2;
    __half* h_ipkw  = hs + OH_IPKW;
    __half* h_ipvw  = hs + OH_IPVW;
    __half* h_ip    = hs + OH_IP;
    __half* h_qr    = hs + OH_QR;
    __half* h_kr    = hs + OH_KR;
    __half* h_qnr   = hs + OH_QNR;
    __half* h_vt    = hs + OH_VT;
    __half* h_P     = hs + OH_P;
    __half* h_ipk   = hs + OH_IPK;
    __half* h_ipvt  = hs + OH_IPVT;
    __half* h_P2    = hs + OH_P2;
    __half* h_fused = hs + OH_FUSED;

    // 0. weight / input conversions to fp16
    launch_f2h(w1, h_w1, (size_t)W1N * HID);
    launch_f2h(w2, h_w2, (size_t)HID * FW);
    launch_f2h(ipkw, h_ipkw, (size_t)HID * CTX);
    launch_f2h(ipvw, h_ipvw, (size_t)HID * CTX);
    launch_f2h(image_proj, h_ip, (size_t)LIP * CTX);

    // 1. modulation vector
    mod_gemv_kernel<<<(3 * HID) / 8, 256>>>(vec, mod_w, mod_b, mod);
    // 2. layernorm + modulate -> half
    ln_mod_kernel<<<L, 256>>>(x, mod, h_xmod);
    // 3. linear1: h = xmod @ w1^T + b1   (2048 x 21504 x 3072)
    launch_gemm(h_xmod, h_w1, hbuf, b1, L, W1N, HID, HID, HID, W1N, 0, 0, 0, 1, 16);
    // 4. rmsnorm + rope + repack -> half
    rms_rope_kernel<<<(H * L) / 8, 256>>>(hbuf, pe, qsc, ksc, h_qr, h_kr, h_qnr, h_vt);
    // 5. ip_k / ip_v projections (64 x 3072 x 4096)
    launch_gemm(h_ip, h_ipkw, ipkr, nullptr, LIP, HID, CTX, CTX, CTX, HID, 0, 0, 0, 1, 1);
    launch_gemm(h_ip, h_ipvw, ipvr, nullptr, LIP, HID, CTX, CTX, CTX, HID, 0, 0, 0, 1, 1);
    repack_ip_kernel<<<(H * LIP * D) / 256, 256>>>(ipkr, ipvr, h_ipk, h_ipvt);
    // 6. S1 = q_rope @ k_rope^T (batched over heads)
    launch_gemm(h_qr, h_kr, Sbuf, nullptr, L, L, D, D, D, L,
                (size_t)L * D, (size_t)L * D, (size_t)L * L, H, 16);
    // 7. softmax -> half P
    softmax_kernel<<<H * L, 256>>>(Sbuf, h_P, L);
    // 8. attn1 = P @ V
    launch_gemm(h_P, h_vt, attn1, nullptr, L, D, L, L, L, D,
                (size_t)L * L, (size_t)D * L, (size_t)L * D, H, 16);
    // 9. S2 = q_nr @ ip_k^T
    launch_gemm(h_qnr, h_ipk, S2, nullptr, L, LIP, D, D, D, LIP,
                (size_t)L * D, (size_t)LIP * D, (size_t)L * LIP, H, 16);
    // 10. softmax (rows of 64) -> half P2
    softmax_kernel<<<H * L, 256>>>(S2, h_P2, LIP);
    // 11. ip_attn = P2 @ ip_v
    launch_gemm(h_P2, h_ipvt, ipattn, nullptr, L, D, LIP, LIP, LIP, D,
                (size_t)L * LIP, (size_t)D * LIP, (size_t)L * D, H, 16);
    // 12. fused = concat(attn_out, gelu(mlp)) -> half
    fuse_kernel<<<dim3(FW / 256, L), 256>>>(attn1, ipattn, ip_scale, hbuf, h_fused);
    // 13. linear2: y = fused @ w2^T + b2  (2048 x 3072 x 15360)
    launch_gemm(h_fused, h_w2, ybuf, b2, L, HID, FW, FW, FW, HID, 0, 0, 0, 1, 8);
    // 14. out = x + gate * y
    final_kernel<<<dim3(HID / 256, L), 256>>>(x, mod, ybuf, out);
}

// round 6
// speedup vs baseline: 1.1310x; 1.1310x over previous
#include <cuda_runtime.h>
#include <cuda_fp16.h>
#include <cstdint>
#include <cstddef>

// ---------------------------------------------------------------------------
// Problem dims
// ---------------------------------------------------------------------------
constexpr int L    = 2048;
constexpr int HID  = 3072;
constexpr int H    = 24;
constexpr int D    = 128;
constexpr int LIP  = 64;
constexpr int CTX  = 4096;
constexpr int W1N  = 3 * HID + 4 * HID;   // 21504
constexpr int MLPD = 4 * HID;             // 12288
constexpr int FW   = HID + MLPD;          // 15360

// ---------------------------------------------------------------------------
// Float scratch
// ---------------------------------------------------------------------------
constexpr size_t O_MOD   = 0;                                   // 9216
constexpr size_t O_H     = O_MOD   + (size_t)3 * HID;           // L*W1N
constexpr size_t O_S     = O_H     + (size_t)L * W1N;           // H*L*L
constexpr size_t O_ATTN1 = O_S     + (size_t)H * L * L;         // H*L*D
constexpr size_t O_IPKR  = O_ATTN1 + (size_t)H * L * D;         // LIP*HID
constexpr size_t O_IPVR  = O_IPKR  + (size_t)LIP * HID;
constexpr size_t O_S2    = O_IPVR  + (size_t)LIP * HID;         // H*L*LIP
constexpr size_t O_IPA   = O_S2    + (size_t)H * L * LIP;       // H*L*D
constexpr size_t O_Y     = O_IPA   + (size_t)H * L * D;         // L*HID
constexpr size_t SCRATCH_F = O_Y + (size_t)L * HID;

__device__ __align__(16) float g_scratch[SCRATCH_F];

// ---------------------------------------------------------------------------
// Half scratch
// ---------------------------------------------------------------------------
constexpr size_t HQ = (size_t)H * L * D;
constexpr size_t OH_XMOD  = 0;                                   // L*HID
constexpr size_t OH_W1    = OH_XMOD  + (size_t)L * HID;          // W1N*HID
constexpr size_t OH_W2    = OH_W1    + (size_t)W1N * HID;        // HID*FW
constexpr size_t OH_IPKW  = OH_W2    + (size_t)HID * FW;         // HID*CTX
constexpr size_t OH_IPVW  = OH_IPKW  + (size_t)HID * CTX;
constexpr size_t OH_IP    = OH_IPVW  + (size_t)HID * CTX;        // LIP*CTX
constexpr size_t OH_QR    = OH_IP    + (size_t)LIP * CTX;        // HQ
constexpr size_t OH_KR    = OH_QR    + HQ;
constexpr size_t OH_QNR   = OH_KR    + HQ;
constexpr size_t OH_VT    = OH_QNR   + HQ;
constexpr size_t OH_P     = OH_VT    + HQ;                       // H*L*L
constexpr size_t OH_IPK   = OH_P     + (size_t)H * L * L;        // H*LIP*D
constexpr size_t OH_IPVT  = OH_IPK   + (size_t)H * LIP * D;
constexpr size_t OH_P2    = OH_IPVT  + (size_t)H * LIP * D;      // H*L*LIP
constexpr size_t OH_FUSED = OH_P2    + (size_t)H * L * LIP;      // L*FW
constexpr size_t SCRATCH_H = OH_FUSED + (size_t)L * FW;

__device__ __align__(16) __half g_hscratch[SCRATCH_H];

// ---------------------------------------------------------------------------
// Helpers
// ---------------------------------------------------------------------------
__device__ __forceinline__ void mma16(float* c, const uint32_t* a,
                                      uint32_t b0, uint32_t b1) {
    asm volatile(
        "mma.sync.aligned.m16n8k16.row.col.f32.f16.f16.f32 "
        "{%0,%1,%2,%3}, {%4,%5,%6,%7}, {%8,%9}, {%0,%1,%2,%3};\n"
        : "+f"(c[0]), "+f"(c[1]), "+f"(c[2]), "+f"(c[3])
        : "r"(a[0]), "r"(a[1]), "r"(a[2]), "r"(a[3]),
          "r"(b0), "r"(b1));
}

__device__ __forceinline__ void ldsm_x4(uint32_t* r, uint32_t addr) {
    asm volatile("ldmatrix.sync.aligned.m8n8.x4.shared.b16 {%0,%1,%2,%3}, [%4];"
                 : "=r"(r[0]), "=r"(r[1]), "=r"(r[2]), "=r"(r[3])
                 : "r"(addr));
}

__device__ __forceinline__ void cp_async16(uint32_t dst, const void* src, bool pred) {
    int bytes = pred ? 16 : 0;
    asm volatile("cp.async.cg.shared.global [%0], [%1], 16, %2;\n"
                 :: "r"(dst), "l"(src), "r"(bytes));
}

__device__ __forceinline__ float blockReduceSum(float v, float* sh) {
    #pragma unroll
    for (int o = 16; o; o >>= 1) v += __shfl_xor_sync(0xffffffffu, v, o);
    int lane = threadIdx.x & 31, w = threadIdx.x >> 5;
    __syncthreads();
    if (lane == 0) sh[w] = v;
    __syncthreads();
    float r = 0.f;
    int nw = blockDim.x >> 5;
    for (int i = 0; i < nw; i++) r += sh[i];
    return r;
}

__device__ __forceinline__ float blockReduceMax(float v, float* sh) {
    #pragma unroll
    for (int o = 16; o; o >>= 1) v = fmaxf(v, __shfl_xor_sync(0xffffffffu, v, o));
    int lane = threadIdx.x & 31, w = threadIdx.x >> 5;
    __syncthreads();
    if (lane == 0) sh[w] = v;
    __syncthreads();
    float r = -INFINITY;
    int nw = blockDim.x >> 5;
    for (int i = 0; i < nw; i++) r = fmaxf(r, sh[i]);
    return r;
}

__device__ __forceinline__ float gelu_tanh(float x) {
    float t  = 0.7978845608028654f * (x + 0.044715f * x * x * x);
    float th = 1.f - 2.f / (__expf(2.f * t) + 1.f);
    return 0.5f * x * (1.0f + th);
}

// ---------------------------------------------------------------------------
// fp16 GEMM: C[M,N](f32) = A[M,K](f16,row) * B[N,K](f16,row)^T (+ bias)
// 128x128x32 tile, 256 threads (2x4 warps, warp tile 64x32),
// cp.async 4-stage ring (prefetch distance 3), ldmatrix fragment loads.
// Row stride in smem: 80B (64B data + 16B pad) -> conflict-free LDSM phases.
// Dynamic smem 4 * 20KB = 80KB -> 2 CTAs/SM.
// ---------------------------------------------------------------------------
constexpr int GSTAGES   = 4;
constexpr int ROWB      = 80;                   // bytes per smem row
constexpr int TILE_B    = 128 * ROWB;           // 10240 bytes per matrix tile
constexpr int STAGE_B   = 2 * TILE_B;           // 20480 bytes per stage
constexpr uint32_t GEMM_SMEM = GSTAGES * STAGE_B;   // 80KB

__global__ void __launch_bounds__(256, 2) gemm_f16_kernel(
    const __half* __restrict__ A, const __half* __restrict__ B,
    float* __restrict__ C, const float* __restrict__ bias,
    int M, int N, int K, int lda, int ldb, int ldc,
    size_t sA, size_t sB, size_t sC,
    int nTiles, int mc)
{
    extern __shared__ __align__(128) uint8_t dsm[];
    uint32_t smBase = (uint32_t)__cvta_generic_to_shared(dsm);

    A += (size_t)blockIdx.z * sA;
    B += (size_t)blockIdx.z * sB;
    C += (size_t)blockIdx.z * sC;

    int bx    = blockIdx.x;
    int per   = mc * nTiles;
    int chunk = bx / per;
    int rem   = bx - chunk * per;
    int nTile = rem / mc;
    int mTile = chunk * mc + (rem - nTile * mc);
    int aBase = mTile * 128;
    int bBase = nTile * 128;

    int tid  = threadIdx.x;
    int lane = tid & 31, warp = tid >> 5;
    int wm   = warp >> 2, wn = warp & 3;

    int kt = K >> 5;

    // cp.async mapping: 2 rows per thread per matrix, 16B chunks
    int r0  = tid >> 2;          // 0..63
    int r1  = r0 + 64;           // 64..127
    int c16 = tid & 3;           // 16B chunk within 64B row
    bool pa0 = aBase + r0 < M, pa1 = aBase + r1 < M;
    bool pb0 = bBase + r0 < N, pb1 = bBase + r1 < N;
    const __half* Ap0 = A + (size_t)(pa0 ? aBase + r0 : 0) * lda + c16 * 8;
    const __half* Ap1 = A + (size_t)(pa1 ? aBase + r1 : 0) * lda + c16 * 8;
    const __half* Bp0 = B + (size_t)(pb0 ? bBase + r0 : 0) * ldb + c16 * 8;
    const __half* Bp1 = B + (size_t)(pb1 ? bBase + r1 : 0) * ldb + c16 * 8;

    uint32_t off0 = (uint32_t)(r0 * ROWB + c16 * 16);
    uint32_t off1 = (uint32_t)(r1 * ROWB + c16 * 16);

    // ldmatrix source offsets (within a stage)
    uint32_t aOff = (uint32_t)((wm * 64 + (lane & 15)) * ROWB + (lane >> 4) * 16);
    uint32_t bOff = (uint32_t)(TILE_B + (wn * 32 + (lane & 15)) * ROWB + (lane >> 4) * 16);

#define GEMM_PREF(itv) do {                                                   \
    int _it = (itv);                                                          \
    if (_it < kt) {                                                           \
        int _ko = _it << 5;                                                   \
        uint32_t _sA = smBase + (uint32_t)(_it % GSTAGES) * STAGE_B;          \
        uint32_t _sB = _sA + (uint32_t)TILE_B;                                \
        cp_async16(_sA + off0, Ap0 + _ko, pa0);                               \
        cp_async16(_sA + off1, Ap1 + _ko, pa1);                               \
        cp_async16(_sB + off0, Bp0 + _ko, pb0);                               \
        cp_async16(_sB + off1, Bp1 + _ko, pb1);                               \
    }                                                                         \
    asm volatile("cp.async.commit_group;\n" ::);                              \
} while (0)

    float acc[4][4][4];
    #pragma unroll
    for (int i = 0; i < 4; i++)
        #pragma unroll
        for (int j = 0; j < 4; j++)
            #pragma unroll
            for (int t = 0; t < 4; t++) acc[i][j][t] = 0.f;

    GEMM_PREF(0);
    GEMM_PREF(1);
    GEMM_PREF(2);

    for (int it = 0; it < kt; ++it) {
        asm volatile("cp.async.wait_group 2;\n" ::);
        __syncthreads();
        GEMM_PREF(it + 3);

        uint32_t stage = smBase + (uint32_t)(it % GSTAGES) * STAGE_B;
        uint32_t aA = stage + aOff;
        uint32_t bA = stage + bOff;

        #pragma unroll
        for (int kk = 0; kk < 2; kk++) {              // two k16 steps per BK=32
            uint32_t a[4][4], b[2][4];
            #pragma unroll
            for (int mt = 0; mt < 4; mt++)
                ldsm_x4(a[mt], aA + mt * (16 * ROWB) + kk * 32);
            #pragma unroll
            for (int np = 0; np < 2; np++)
                ldsm_x4(b[np], bA + np * (16 * ROWB) + kk * 32);
            #pragma unroll
            for (int mt = 0; mt < 4; mt++)
                #pragma unroll
                for (int nt = 0; nt < 4; nt++)
                    mma16(acc[mt][nt], a[mt],
                          b[nt >> 1][nt & 1], b[nt >> 1][(nt & 1) + 2]);
        }
    }
#undef GEMM_PREF

    // Epilogue
    int gid = lane >> 2, tig = lane & 3;
    #pragma unroll
    for (int mt = 0; mt < 4; mt++) {
        #pragma unroll
        for (int nt = 0; nt < 4; nt++) {
            int row = aBase + wm * 64 + mt * 16 + gid;
            int col = bBase + wn * 32 + nt * 8 + tig * 2;
            if (col < N) {
                float b0 = 0.f, b1 = 0.f;
                if (bias) { b0 = bias[col]; b1 = bias[col + 1]; }
                if (row < M) {
                    C[(size_t)row * ldc + col]     = acc[mt][nt][0] + b0;
                    C[(size_t)row * ldc + col + 1] = acc[mt][nt][1] + b1;
                }
                if (row + 8 < M) {
                    C[(size_t)(row + 8) * ldc + col]     = acc[mt][nt][2] + b0;
                    C[(size_t)(row + 8) * ldc + col + 1] = acc[mt][nt][3] + b1;
                }
            }
        }
    }
}

// ---------------------------------------------------------------------------
// float -> half conversion (n divisible by 4)
// ---------------------------------------------------------------------------
__global__ __launch_bounds__(256) void f2h_kernel(
    const float* __restrict__ in, __half* __restrict__ out, int n)
{
    int i = (blockIdx.x * 256 + threadIdx.x) * 4;
    if (i < n) {
        float4 v = *(const float4*)(in + i);
        *(__half2*)(out + i)     = __floats2half2_rn(v.x, v.y);
        *(__half2*)(out + i + 2) = __floats2half2_rn(v.z, v.w);
    }
}

// ---------------------------------------------------------------------------
// mod = silu(vec) @ mod_lin_w^T + mod_lin_b
// ---------------------------------------------------------------------------
__global__ __launch_bounds__(256) void mod_gemv_kernel(
    const float* __restrict__ vec, const float* __restrict__ W,
    const float* __restrict__ b, float* __restrict__ mod)
{
    __shared__ float sv[HID];
    int tid = threadIdx.x;
    for (int i = tid; i < HID; i += 256) {
        float x = vec[i];
        sv[i] = x / (1.f + __expf(-x));
    }
    __syncthreads();
    int warp = tid >> 5, lane = tid & 31;
    int n = blockIdx.x * 8 + warp;
    const float* wrow = W + (size_t)n * HID;
    float s = 0.f;
    for (int k = lane * 4; k < HID; k += 128) {
        float4 w4 = *(const float4*)(wrow + k);
        s += sv[k] * w4.x + sv[k + 1] * w4.y + sv[k + 2] * w4.z + sv[k + 3] * w4.w;
    }
    #pragma unroll
    for (int o = 16; o; o >>= 1) s += __shfl_xor_sync(0xffffffffu, s, o);
    if (lane == 0) mod[n] = s + b[n];
}

// ---------------------------------------------------------------------------
// x_mod = (1+scale)*layernorm(x) + shift  -> half
// ---------------------------------------------------------------------------
__global__ __launch_bounds__(256) void ln_mod_kernel(
    const float* __restrict__ x, const float* __restrict__ mod,
    __half* __restrict__ xmod)
{
    __shared__ float sh[8];
    int l = blockIdx.x, tid = threadIdx.x;
    const float* row = x + (size_t)l * HID;
    float v[12];
    float s = 0.f, sq = 0.f;
    #pragma unroll
    for (int i = 0; i < 12; i++) {
        v[i] = row[tid + i * 256];
        s += v[i];
        sq += v[i] * v[i];
    }
    s  = blockReduceSum(s, sh);
    sq = blockReduceSum(sq, sh);
    float mu   = s * (1.f / HID);
    float var  = sq * (1.f / HID) - mu * mu;
    float rstd = rsqrtf(var + 1e-6f);
    #pragma unroll
    for (int i = 0; i < 12; i++) {
        int c = tid + i * 256;
        float xn = (v[i] - mu) * rstd;
        xmod[(size_t)l * HID + c] = __float2half((1.f + mod[HID + c]) * xn + mod[c]);
    }
}

// ---------------------------------------------------------------------------
// rmsnorm(q,k) + rope + repack (half outputs). One warp per (l, head).
// q outputs pre-scaled by 1/sqrt(D).
// ---------------------------------------------------------------------------
__global__ __launch_bounds__(256) void rms_rope_kernel(
    const float* __restrict__ h, const float* __restrict__ pe,
    const float* __restrict__ qsc, const float* __restrict__ ksc,
    __half* __restrict__ qr, __half* __restrict__ kr,
    __half* __restrict__ qnr, __half* __restrict__ vt)
{
    int tid = threadIdx.x, lane = tid & 31, warp = tid >> 5;
    int g = blockIdx.x * 8 + warp;          // 0 .. H*L-1
    int l = g / H, head = g - l * H;

    const float* base = h + (size_t)l * W1N + head * D + lane * 4;
    float4 q = *(const float4*)(base);
    float4 k = *(const float4*)(base + HID);
    float4 v = *(const float4*)(base + 2 * HID);

    float sq = q.x * q.x + q.y * q.y + q.z * q.z + q.w * q.w;
    float sk = k.x * k.x + k.y * k.y + k.z * k.z + k.w * k.w;
    #pragma unroll
    for (int o = 16; o; o >>= 1) {
        sq += __shfl_xor_sync(0xffffffffu, sq, o);
        sk += __shfl_xor_sync(0xffffffffu, sk, o);
    }
    float rq = rsqrtf(sq * (1.f / D) + 1e-6f) * 0.08838834764831845f;
    float rk = rsqrtf(sk * (1.f / D) + 1e-6f);

    float4 qs4 = *(const float4*)(qsc + lane * 4);
    float4 ks4 = *(const float4*)(ksc + lane * 4);
    float4 qn = make_float4(q.x * rq * qs4.x, q.y * rq * qs4.y,
                            q.z * rq * qs4.z, q.w * rq * qs4.w);
    float4 kn = make_float4(k.x * rk * ks4.x, k.y * rk * ks4.y,
                            k.z * rk * ks4.z, k.w * rk * ks4.w);

    size_t oidx = ((size_t)head * L + l) * D + lane * 4;
    *(__half2*)(qnr + oidx)     = __floats2half2_rn(qn.x, qn.y);
    *(__half2*)(qnr + oidx + 2) = __floats2half2_rn(qn.z, qn.w);

    const float* pb = pe + ((size_t)l * (D / 2) + lane * 2) * 4;
    float4 p0 = *(const float4*)(pb);
    float4 p1 = *(const float4*)(pb + 4);

    float4 qo, ko;
    qo.x = p0.x * qn.x + p0.y * qn.y;  qo.y = p0.z * qn.x + p0.w * qn.y;
    qo.z = p1.x * qn.z + p1.y * qn.w;  qo.w = p1.z * qn.z + p1.w * qn.w;
    ko.x = p0.x * kn.x + p0.y * kn.y;  ko.y = p0.z * kn.x + p0.w * kn.y;
    ko.z = p1.x * kn.z + p1.y * kn.w;  ko.w = p1.z * kn.z + p1.w * kn.w;

    *(__half2*)(qr + oidx)     = __floats2half2_rn(qo.x, qo.y);
    *(__half2*)(qr + oidx + 2) = __floats2half2_rn(qo.z, qo.w);
    *(__half2*)(kr + oidx)     = __floats2half2_rn(ko.x, ko.y);
    *(__half2*)(kr + oidx + 2) = __floats2half2_rn(ko.z, ko.w);

    int d = lane * 4;
    size_t vb = ((size_t)head * D + d) * L + l;
    vt[vb]         = __float2half(v.x);
    vt[vb + L]     = __float2half(v.y);
    vt[vb + 2 * L] = __float2half(v.z);
    vt[vb + 3 * L] = __float2half(v.w);
}

// ---------------------------------------------------------------------------
// repack ip_k / ip_v GEMM outputs into per-head half layouts
// ---------------------------------------------------------------------------
__global__ __launch_bounds__(256) void repack_ip_kernel(
    const float* __restrict__ kraw, const float* __restrict__ vraw,
    __half* __restrict__ ipk, __half* __restrict__ ipvt)
{
    int i = blockIdx.x * 256 + threadIdx.x;       // < H*LIP*D
    int d = i & (D - 1);
    int lip = (i >> 7) & (LIP - 1);
    int head = i >> 13;
    size_t src = (size_t)lip * HID + head * D + d;
    ipk[((size_t)head * LIP + lip) * D + d]  = __float2half(kraw[src]);
    ipvt[((size_t)head * D + d) * LIP + lip] = __float2half(vraw[src]);
}

// ---------------------------------------------------------------------------
// row softmax float -> half
// ---------------------------------------------------------------------------
__global__ __launch_bounds__(256) void softmax_kernel(
    const float* __restrict__ S, __half* __restrict__ P, int ncols)
{
    __shared__ float sh[8];
    size_t row = blockIdx.x;
    const float* p = S + row * (size_t)ncols;
    __half* po = P + row * (size_t)ncols;
    float v[8];
    int cnt = 0;
    float m = -INFINITY;
    for (int c = threadIdx.x; c < ncols; c += 256) {
        v[cnt] = p[c];
        m = fmaxf(m, v[cnt]);
        cnt++;
    }
    m = blockReduceMax(m, sh);
    float s = 0.f;
    for (int i = 0; i < cnt; i++) {
        v[i] = __expf(v[i] - m);
        s += v[i];
    }
    s = blockReduceSum(s, sh);
    float inv = 1.f / s;
    cnt = 0;
    for (int c = threadIdx.x; c < ncols; c += 256) po[c] = __float2half(v[cnt++] * inv);
}

// ---------------------------------------------------------------------------
// fused = concat(attn1 + ip_scale*ip_attn, gelu(mlp)) -> half
// ---------------------------------------------------------------------------
__global__ __launch_bounds__(256) void fuse_kernel(
    const float* __restrict__ attn1, const float* __restrict__ ipattn,
    const float* __restrict__ ip_scale, const float* __restrict__ h,
    __half* __restrict__ fused)
{
    int c = blockIdx.x * 256 + threadIdx.x;   // 0..FW-1
    int l = blockIdx.y;
    float val;
    if (c < HID) {
        int head = c >> 7, d = c & (D - 1);
        size_t idx = ((size_t)head * L + l) * D + d;
        val = attn1[idx] + ip_scale[0] * ipattn[idx];
    } else {
        val = gelu_tanh(h[(size_t)l * W1N + 3 * HID + (c - HID)]);
    }
    fused[(size_t)l * FW + c] = __float2half(val);
}

// ---------------------------------------------------------------------------
// out = x + gate * y
// ---------------------------------------------------------------------------
__global__ __launch_bounds__(256) void final_kernel(
    const float* __restrict__ x, const float* __restrict__ mod,
    const float* __restrict__ y, float* __restrict__ out)
{
    int c = blockIdx.x * 256 + threadIdx.x;
    int l = blockIdx.y;
    size_t idx = (size_t)l * HID + c;
    out[idx] = x[idx] + mod[2 * HID + c] * y[idx];
}

// ---------------------------------------------------------------------------
// host side
// ---------------------------------------------------------------------------
static void launch_gemm(const __half* A, const __half* B, float* C, const float* bias,
                        int M, int N, int K, int lda, int ldb, int ldc,
                        size_t sA, size_t sB, size_t sC, int batch, int mc)
{
    int mTiles = (M + 127) / 128, nTiles = (N + 127) / 128;
    if (mc > mTiles) mc = mTiles;
    dim3 grid(mTiles * nTiles, 1, batch);
    gemm_f16_kernel<<<grid, 256, GEMM_SMEM>>>(A, B, C, bias, M, N, K, lda, ldb, ldc,
                                              sA, sB, sC, nTiles, mc);
}

static void launch_f2h(const float* in, __half* out, size_t n)
{
    int blocks = (int)((n / 4 + 255) / 256);
    f2h_kernel<<<blocks, 256>>>(in, out, (int)n);
}

extern "C" void kernel_launch(void* const* d_in, const int* in_sizes, int n_in,
                              void* d_out, int out_size)
{
    const float* x          = (const float*)d_in[0];
    const float* vec        = (const float*)d_in[1];
    const float* pe         = (const float*)d_in[2];
    const float* image_proj = (const float*)d_in[3];
    const float* ip_scale   = (const float*)d_in[4];
    const float* mod_w      = (const float*)d_in[5];
    const float* mod_b      = (const float*)d_in[6];
    const float* w1         = (const float*)d_in[7];
    const float* b1         = (const float*)d_in[8];
    const float* w2         = (const float*)d_in[9];
    const float* b2         = (const float*)d_in[10];
    const float* qsc        = (const float*)d_in[11];
    const float* ksc        = (const float*)d_in[12];
    const float* ipkw       = (const float*)d_in[13];
    const float* ipvw       = (const float*)d_in[14];
    float* out = (float*)d_out;

    cudaFuncSetAttribute(gemm_f16_kernel,
                         cudaFuncAttributeMaxDynamicSharedMemorySize, GEMM_SMEM);

    float* sc = nullptr;
    cudaGetSymbolAddress((void**)&sc, g_scratch);
    __half* hs = nullptr;
    cudaGetSymbolAddress((void**)&hs, g_hscratch);

    float* mod    = sc + O_MOD;
    float* hbuf   = sc + O_H;
    float* Sbuf   = sc + O_S;
    float* attn1  = sc + O_ATTN1;
    float* ipkr   = sc + O_IPKR;
    float* ipvr   = sc + O_IPVR;
    float* S2     = sc + O_S2;
    float* ipattn = sc + O_IPA;
    float* ybuf   = sc + O_Y;

    __half* h_xmod  = hs + OH_XMOD;
    __half* h_w1    = hs + OH_W1;
    __half* h_w2    = hs + OH_W2;
    __half* h_ipkw  = hs + OH_IPKW;
    __half* h_ipvw  = hs + OH_IPVW;
    __half* h_ip    = hs + OH_IP;
    __half* h_qr    = hs + OH_QR;
    __half* h_kr    = hs + OH_KR;
    __half* h_qnr   = hs + OH_QNR;
    __half* h_vt    = hs + OH_VT;
    __half* h_P     = hs + OH_P;
    __half* h_ipk   = hs + OH_IPK;
    __half* h_ipvt  = hs + OH_IPVT;
    __half* h_P2    = hs + OH_P2;
    __half* h_fused = hs + OH_FUSED;

    // Launch order arranged so that ncu (-s 5 -c 1) profiles linear1 (#5).
    // [0] modulation vector
    mod_gemv_kernel<<<(3 * HID) / 8, 256>>>(vec, mod_w, mod_b, mod);
    // [1] w1 -> half
    launch_f2h(w1, h_w1, (size_t)W1N * HID);
    // [2] layernorm + modulate -> half
    ln_mod_kernel<<<L, 256>>>(x, mod, h_xmod);
    // [3] w2 -> half
    launch_f2h(w2, h_w2, (size_t)HID * FW);
    // [4] ipkw -> half
    launch_f2h(ipkw, h_ipkw, (size_t)HID * CTX);
    // [5] linear1: h = xmod @ w1^T + b1   (2048 x 21504 x 3072)
    launch_gemm(h_xmod, h_w1, hbuf, b1, L, W1N, HID, HID, HID, W1N, 0, 0, 0, 1, 16);
    // remaining conversions
    launch_f2h(ipvw, h_ipvw, (size_t)HID * CTX);
    launch_f2h(image_proj, h_ip, (size_t)LIP * CTX);
    // rmsnorm + rope + repack -> half
    rms_rope_kernel<<<(H * L) / 8, 256>>>(hbuf, pe, qsc, ksc, h_qr, h_kr, h_qnr, h_vt);
    // ip_k / ip_v projections (64 x 3072 x 4096)
    launch_gemm(h_ip, h_ipkw, ipkr, nullptr, LIP, HID, CTX, CTX, CTX, HID, 0, 0, 0, 1, 1);
    launch_gemm(h_ip, h_ipvw, ipvr, nullptr, LIP, HID, CTX, CTX, CTX, HID, 0, 0, 0, 1, 1);
    repack_ip_kernel<<<(H * LIP * D) / 256, 256>>>(ipkr, ipvr, h_ipk, h_ipvt);
    // S1 = q_rope @ k_rope^T (batched over heads)
    launch_gemm(h_qr, h_kr, Sbuf, nullptr, L, L, D, D, D, L,
                (size_t)L * D, (size_t)L * D, (size_t)L * L, H, 16);
    // softmax -> half P
    softmax_kernel<<<H * L, 256>>>(Sbuf, h_P, L);
    // attn1 = P @ V
    launch_gemm(h_P, h_vt, attn1, nullptr, L, D, L, L, L, D,
                (size_t)L * L, (size_t)D * L, (size_t)L * D, H, 16);
    // S2 = q_nr @ ip_k^T
    launch_gemm(h_qnr, h_ipk, S2, nullptr, L, LIP, D, D, D, LIP,
                (size_t)L * D, (size_t)LIP * D, (size_t)L * LIP, H, 16);
    // softmax (rows of 64) -> half P2
    softmax_kernel<<<H * L, 256>>>(S2, h_P2, LIP);
    // ip_attn = P2 @ ip_v
    launch_gemm(h_P2, h_ipvt, ipattn, nullptr, L, D, LIP, LIP, LIP, D,
                (size_t)L * LIP, (size_t)D * LIP, (size_t)L * D, H, 16);
    // fused = concat(attn_out, gelu(mlp)) -> half
    fuse_kernel<<<dim3(FW / 256, L), 256>>>(attn1, ipattn, ip_scale, hbuf, h_fused);
    // linear2: y = fused @ w2^T + b2  (2048 x 3072 x 15360)
    launch_gemm(h_fused, h_w2, ybuf, b2, L, HID, FW, FW, FW, HID, 0, 0, 0, 1, 8);
    // out = x + gate * y
    final_kernel<<<dim3(HID / 256, L), 256>>>(x, mod, ybuf, out);
}